// round 16
// baseline (speedup 1.0000x reference)
#include <cuda_runtime.h>

// ============================================================================
// Compile-time real Clebsch-Gordan coefficients (constexpr port of reference)
// ============================================================================

__host__ __device__ constexpr double cfact(int n) {
    double r = 1.0;
    for (int k = 2; k <= n; ++k) r *= (double)k;
    return r;
}

__host__ __device__ constexpr double csqrt(double x) {
    if (x <= 0.0) return 0.0;
    double g = x > 1.0 ? x : 1.0;
    for (int it = 0; it < 100; ++it) g = 0.5 * (g + x / g);
    return g;
}

__host__ __device__ constexpr int imax3(int a, int b, int c) { int m = a; if (b > m) m = b; if (c > m) m = c; return m; }
__host__ __device__ constexpr int imin3(int a, int b, int c) { int m = a; if (b < m) m = b; if (c < m) m = c; return m; }
__host__ __device__ constexpr int iabs_(int a) { return a < 0 ? -a : a; }
__host__ __device__ constexpr double dabs_(double a) { return a < 0.0 ? -a : a; }

// Complex Clebsch-Gordan <l1 m1 l2 m2 | l3 m3> via Racah formula
__host__ __device__ constexpr double cg_complex(int l1, int m1, int l2, int m2, int l3, int m3) {
    if (m1 + m2 != m3 || l3 < iabs_(l1 - l2) || l3 > l1 + l2) return 0.0;
    double pre = csqrt((double)(2 * l3 + 1) * cfact(l1 + l2 - l3) * cfact(l1 - l2 + l3) *
                       cfact(-l1 + l2 + l3) / cfact(l1 + l2 + l3 + 1));
    pre *= csqrt(cfact(l1 + m1) * cfact(l1 - m1) * cfact(l2 + m2) * cfact(l2 - m2) *
                 cfact(l3 + m3) * cfact(l3 - m3));
    int kmin = imax3(0, l2 - l3 - m1, l1 - l3 + m2);
    int kmax = imin3(l1 + l2 - l3, l1 - m1, l2 + m2);
    double s = 0.0;
    for (int k = kmin; k <= kmax; ++k) {
        double d = cfact(k) * cfact(l1 + l2 - l3 - k) * cfact(l1 - m1 - k) *
                   cfact(l2 + m2 - k) * cfact(l3 - l2 + m1 + k) * cfact(l3 - l1 - m2 + k);
        s += ((k & 1) ? -1.0 : 1.0) / d;
    }
    return pre * s;
}

template <int L1, int L2, int L3>
struct CGT {
    double v[2 * L1 + 1][2 * L2 + 1][2 * L3 + 1];
};

// Real-basis CG tensor (exact port of reference: .imag if it dominates, else .real)
template <int L1, int L2, int L3>
__host__ __device__ constexpr CGT<L1, L2, L3> make_cg() {
    constexpr int NA = 2 * L1 + 1, NB = 2 * L2 + 1, NC = 2 * L3 + 1;
    const double is2 = 1.0 / csqrt(2.0);

    double Ur[3][7][7] = {};
    double Ui[3][7][7] = {};
    int Ls[3] = {L1, L2, L3};
    for (int t = 0; t < 3; ++t) {
        int l = Ls[t];
        for (int mp = -l; mp <= l; ++mp) {
            int r = mp + l;
            if (mp > 0) {
                Ur[t][r][mp + l]  = ((mp & 1) ? -1.0 : 1.0) * is2;
                Ur[t][r][-mp + l] = is2;
            } else if (mp == 0) {
                Ur[t][r][l] = 1.0;
            } else {
                Ui[t][r][mp + l]  = is2;
                Ui[t][r][-mp + l] = -(((-mp) & 1) ? -1.0 : 1.0) * is2;
            }
        }
    }

    double Cc[7][7][7] = {};
    for (int m = 0; m < NA; ++m)
        for (int n = 0; n < NB; ++n)
            for (int o = 0; o < NC; ++o)
                Cc[m][n][o] = cg_complex(L1, m - L1, L2, n - L2, L3, o - L3);

    double Tre[NA][NB][NC] = {};
    double Tim[NA][NB][NC] = {};
    double maxre = 0.0, maxim = 0.0;
    for (int a = 0; a < NA; ++a)
        for (int b = 0; b < NB; ++b)
            for (int c = 0; c < NC; ++c) {
                double are = 0.0, aim = 0.0;
                for (int m = 0; m < NA; ++m)
                    for (int n = 0; n < NB; ++n) {
                        int o = (m - L1) + (n - L2) + L3;
                        if (o < 0 || o >= NC) continue;
                        double cc = Cc[m][n][o];
                        if (cc == 0.0) continue;
                        double xr = Ur[0][a][m], xi = Ui[0][a][m];
                        double yr = Ur[1][b][n], yi = Ui[1][b][n];
                        double zr = Ur[2][c][o], zi = -Ui[2][c][o];
                        double pr = xr * yr - xi * yi;
                        double pi = xr * yi + xi * yr;
                        double tr = pr * zr - pi * zi;
                        double ti = pr * zi + pi * zr;
                        are += tr * cc;
                        aim += ti * cc;
                    }
                Tre[a][b][c] = are;
                Tim[a][b][c] = aim;
                if (dabs_(are) > maxre) maxre = dabs_(are);
                if (dabs_(aim) > maxim) maxim = dabs_(aim);
            }

    CGT<L1, L2, L3> R = {};
    bool useim = maxim > maxre;
    for (int a = 0; a < NA; ++a)
        for (int b = 0; b < NB; ++b)
            for (int c = 0; c < NC; ++c)
                R.v[a][b][c] = useim ? Tim[a][b][c] : Tre[a][b][c];
    return R;
}

// Exchange sign sigma s.t. T(L2,L1,L3)[b][a][c] == sigma * T(L1,L2,L3)[a][b][c]
template <int L1, int L2, int L3>
__host__ __device__ constexpr double exch_sign() {
    CGT<L1, L2, L3> A = make_cg<L1, L2, L3>();
    CGT<L2, L1, L3> B = make_cg<L2, L1, L3>();
    for (int a = 0; a < 2 * L1 + 1; ++a)
        for (int b = 0; b < 2 * L2 + 1; ++b)
            for (int c = 0; c < 2 * L3 + 1; ++c)
                if (dabs_(A.v[a][b][c]) > 1e-9)
                    return B.v[b][a][c] / A.v[a][b][c];
    return 0.0;
}

// Does the symmetrized (self-coupling) tensor have any nonzero?
template <int L, int L3>
__host__ __device__ constexpr bool sym_any() {
    CGT<L, L, L3> T = make_cg<L, L, L3>();
    for (int a = 0; a < 2 * L + 1; ++a)
        for (int b = a; b < 2 * L + 1; ++b)
            for (int c = 0; c < 2 * L3 + 1; ++c) {
                double w = (a == b) ? T.v[a][b][c] : (T.v[a][b][c] + T.v[b][a][c]);
                if (dabs_(w) > 1e-12) return true;
            }
    return false;
}

// ============================================================================
// Contractions. CG weights are compile-time constants; ~zero terms are DCE'd,
// surviving terms become FFMA with immediate multipliers.
// ============================================================================

template <int L1, int L2, int L3>
__device__ __forceinline__ void acc_path(float scale, const float* u, const float* v, float* o) {
    constexpr CGT<L1, L2, L3> T = make_cg<L1, L2, L3>();
    float tmp[2 * L3 + 1];
#pragma unroll
    for (int c = 0; c < 2 * L3 + 1; ++c) tmp[c] = 0.0f;
#pragma unroll
    for (int a = 0; a < 2 * L1 + 1; ++a) {
#pragma unroll
        for (int b = 0; b < 2 * L2 + 1; ++b) {
            float p = u[a] * v[b];
#pragma unroll
            for (int c = 0; c < 2 * L3 + 1; ++c) {
                constexpr double EPS = 1e-12;
                double wd = T.v[a][b][c];
                if (wd > EPS || wd < -EPS) tmp[c] = fmaf((float)wd, p, tmp[c]);
            }
        }
    }
#pragma unroll
    for (int c = 0; c < 2 * L3 + 1; ++c) o[c] = fmaf(scale, tmp[c], o[c]);
}

// Self-coupling, symmetrized over (a,b): products only for a<=b; fully
// antisymmetric paths drop at compile time.
template <int L, int L3>
__device__ __forceinline__ void acc_sym(float scale, const float* u, float* o) {
    if constexpr (!sym_any<L, L3>()) return;
    constexpr CGT<L, L, L3> T = make_cg<L, L, L3>();
    float tmp[2 * L3 + 1];
#pragma unroll
    for (int c = 0; c < 2 * L3 + 1; ++c) tmp[c] = 0.0f;
#pragma unroll
    for (int a = 0; a < 2 * L + 1; ++a) {
#pragma unroll
        for (int b = a; b < 2 * L + 1; ++b) {
            float p = u[a] * u[b];
#pragma unroll
            for (int c = 0; c < 2 * L3 + 1; ++c) {
                constexpr double EPS = 1e-12;
                double wd = (a == b) ? T.v[a][b][c] : (T.v[a][b][c] + T.v[b][a][c]);
                if (wd > EPS || wd < -EPS) tmp[c] = fmaf((float)wd, p, tmp[c]);
            }
        }
    }
#pragma unroll
    for (int c = 0; c < 2 * L3 + 1; ++c) o[c] = fmaf(scale, tmp[c], o[c]);
}

// ============================================================================
// Kernel. Layout facts (METADATA=[64,48,32], MAX_L=3):
//   OFF_IN = {0,64,208}, DIM_IN=368; OFF_OUT={0,64,208,448}, DIM_OUT=672
//   mix base offsets (PATHS order):
//     (0,0,0):0 (0,1,1):64 (0,2,2):112 (1,0,1):144 (1,1,0):192 (1,1,1):240
//     (1,1,2):288 (1,2,1):336 (1,2,2):368 (1,2,3):400 (2,0,2):432 (2,1,1):464
//     (2,1,2):496 (2,1,3):528 (2,2,0):560 (2,2,1):592 (2,2,2):624 (2,2,3):656
//   keep bases: l0->0, l1->64, l2->112
//
// WARP-AUTONOMOUS, 2 ROWS PER WARP: coefficients (incl. fused mirror-pair
// scales) are loaded ONCE per warp into registers, then two consecutive rows
// are processed through the same private smem slot. Row1's input is
// register-prefetched during row0's compute so its LDG latency is hidden.
// Thread i handles HEAVY channel i (full path set) and LIGHT channel 32+i
// (l0 always; l1 iff i<16). Unique writer per output element; no atomics;
// intra-warp sync only.
// ============================================================================

#define TPB 256
#define WARPS_PB (TPB / 32)   // 8 warps per block
#define ROWS_PW 2             // rows per warp
#define DIN 368               // 92 float4
#define DOUT 672              // 168 float4
#define WSLOT (DIN + DOUT)    // 1040 floats = 260 float4 per warp

__global__ void __launch_bounds__(TPB) selfmix_kernel(
    const float* __restrict__ x, const float* __restrict__ keepc,
    const float* __restrict__ mixc, float* __restrict__ out, int n)
{
    __shared__ float4 smem4[WARPS_PB * WSLOT / 4];   // 33280 B

    int w = threadIdx.x >> 5;
    int lane = threadIdx.x & 31;
    int base = (blockIdx.x * WARPS_PB + w) * ROWS_PW;
    if (base >= n) return;

    float4* xw4 = smem4 + w * (WSLOT / 4);
    float4* ow4 = xw4 + (DIN / 4);
    float* xr = (float*)xw4;
    float* orow = (float*)ow4;

    int i = lane;        // heavy channel
    int j = 32 + i;      // light channel

    constexpr float S011 = (float)exch_sign<0, 1, 1>();
    constexpr float S022 = (float)exch_sign<0, 2, 2>();
    constexpr float S121 = (float)exch_sign<1, 2, 1>();
    constexpr float S122 = (float)exch_sign<1, 2, 2>();
    constexpr float S123 = (float)exch_sign<1, 2, 3>();

    // ---- prefetch row `base` input (3 float4 per lane covers 92 float4) ----
    float4 pf0, pf1, pf2;
    pf2 = make_float4(0.f, 0.f, 0.f, 0.f);
    {
        const float4* xg4 = (const float4*)(x + (long long)base * DIN);
        pf0 = xg4[lane];
        pf1 = xg4[lane + 32];
        if (lane < DIN / 4 - 64) pf2 = xg4[lane + 64];
    }

    // ---- row-invariant coefficients, loaded once per warp ----
    // light channel j
    float kc0j = keepc[j];
    float fm000j = 0.5f * mixc[j];
    float kc1j = 0.f, fm011j = 0.f, fm110j = 0.f, fm112j = 0.f;
    if (i < 16) {
        kc1j   = keepc[64 + j];
        fm011j = 0.5f * (mixc[64 + j] + S011 * mixc[144 + j]);
        fm110j = 0.5f * mixc[192 + j];
        fm112j = 0.5f * mixc[288 + j];
    }
    // heavy channel i
    float kc0i = keepc[i];
    float kc1i = keepc[64 + i];
    float kc2i = keepc[112 + i];
    float fm000i = 0.5f * mixc[i];
    float fm011i = 0.5f * (mixc[64 + i] + S011 * mixc[144 + i]);
    float fm110i = 0.5f * mixc[192 + i];
    float fm112i = 0.5f * mixc[288 + i];
    float fm022i = 0.5f * (mixc[112 + i] + S022 * mixc[432 + i]);
    float fm121i = 0.5f * (mixc[336 + i] + S121 * mixc[464 + i]);
    float fm122i = 0.5f * (mixc[368 + i] + S122 * mixc[496 + i]);
    float fm123i = 0.5f * (mixc[400 + i] + S123 * mixc[528 + i]);
    float fm220i = 0.5f * mixc[560 + i];
    float fm222i = 0.5f * mixc[624 + i];

#pragma unroll
    for (int r = 0; r < ROWS_PW; ++r) {
        int row = base + r;
        if (row >= n) break;

        // ---- stage prefetched input into warp-private smem ----
        xw4[lane] = pf0;
        xw4[lane + 32] = pf1;
        if (lane < DIN / 4 - 64) xw4[lane + 64] = pf2;
        __syncwarp();

        // ---- prefetch next row while computing this one ----
        if (r == 0 && base + 1 < n) {
            const float4* ng4 = (const float4*)(x + (long long)(base + 1) * DIN);
            pf0 = ng4[lane];
            pf1 = ng4[lane + 32];
            if (lane < DIN / 4 - 64) pf2 = ng4[lane + 64];
        }

        // ---------------- LIGHT phase: channel j = 32+i ----------------
        {
            float s2[1] = { xr[j] };
            float o0b[1];
            o0b[0] = s2[0] * kc0j;
            acc_path<0, 0, 0>(fm000j, s2, s2, o0b);

            if (i < 16) {  // l1 channels 32..47
                float u2[3];
#pragma unroll
                for (int m = 0; m < 3; ++m) u2[m] = xr[64 + 3 * j + m];
                float o1b[3];
#pragma unroll
                for (int m = 0; m < 3; ++m) o1b[m] = u2[m] * kc1j;

                acc_path<0, 1, 1>(fm011j, s2, u2, o1b);
                acc_sym<1, 0>(fm110j, u2, o0b);

                float o2b[5];
#pragma unroll
                for (int m = 0; m < 5; ++m) o2b[m] = 0.0f;
                acc_sym<1, 2>(fm112j, u2, o2b);

#pragma unroll
                for (int m = 0; m < 3; ++m) orow[64 + 3 * j + m] = o1b[m];
#pragma unroll
                for (int m = 0; m < 5; ++m) orow[208 + 5 * j + m] = o2b[m];
            }
            orow[j] = o0b[0];
        }

        // ---------------- HEAVY phase: channel i ----------------
        {
            float s[1] = { xr[i] };
            float u[3];
#pragma unroll
            for (int m = 0; m < 3; ++m) u[m] = xr[64 + 3 * i + m];
            float w5[5];
#pragma unroll
            for (int m = 0; m < 5; ++m) w5[m] = xr[208 + 5 * i + m];

            float o0[1];
            o0[0] = s[0] * kc0i;
            acc_path<0, 0, 0>(fm000i, s, s, o0);

            float o1[3];
#pragma unroll
            for (int m = 0; m < 3; ++m) o1[m] = u[m] * kc1i;

            float o2[5];
#pragma unroll
            for (int m = 0; m < 5; ++m) o2[m] = w5[m] * kc2i;

            float o3[7];
#pragma unroll
            for (int m = 0; m < 7; ++m) o3[m] = 0.0f;

            acc_path<0, 1, 1>(fm011i, s, u, o1);
            acc_sym<1, 0>(fm110i, u, o0);
            acc_sym<1, 2>(fm112i, u, o2);

            acc_path<0, 2, 2>(fm022i, s, w5, o2);
            acc_path<1, 2, 1>(fm121i, u, w5, o1);
            acc_path<1, 2, 2>(fm122i, u, w5, o2);
            acc_path<1, 2, 3>(fm123i, u, w5, o3);

            acc_sym<2, 0>(fm220i, w5, o0);
            acc_sym<2, 2>(fm222i, w5, o2);

            orow[i] = o0[0];
#pragma unroll
            for (int m = 0; m < 3; ++m) orow[64 + 3 * i + m] = o1[m];
#pragma unroll
            for (int m = 0; m < 5; ++m) orow[208 + 5 * i + m] = o2[m];
#pragma unroll
            for (int m = 0; m < 7; ++m) orow[448 + 7 * i + m] = o3[m];
        }
        __syncwarp();

        // ---- warp-private staged output store ----
        {
            float4* og4 = (float4*)(out + (long long)row * DOUT);
#pragma unroll
            for (int t = lane; t < DOUT / 4; t += 32) og4[t] = ow4[t];
        }
        __syncwarp();   // protect os (and xs slot) before next iteration reuses them
    }
}

// ============================================================================
// Launch
// ============================================================================
extern "C" void kernel_launch(void* const* d_in, const int* in_sizes, int n_in,
                              void* d_out, int out_size) {
    const float* x     = (const float*)d_in[0];   // [N, 368]
    const float* keepc = (const float*)d_in[1];   // [144]
    const float* mixc  = (const float*)d_in[2];   // [688]
    float* out = (float*)d_out;                   // [N, 672]

    int n = in_sizes[0] / DIN;
    int rows_per_block = WARPS_PB * ROWS_PW;
    int grid = (n + rows_per_block - 1) / rows_per_block;
    selfmix_kernel<<<grid, TPB>>>(x, keepc, mixc, out, n);
}

// round 17
// speedup vs baseline: 1.0921x; 1.0921x over previous
#include <cuda_runtime.h>

// ============================================================================
// Compile-time real Clebsch-Gordan coefficients (constexpr port of reference)
// ============================================================================

__host__ __device__ constexpr double cfact(int n) {
    double r = 1.0;
    for (int k = 2; k <= n; ++k) r *= (double)k;
    return r;
}

__host__ __device__ constexpr double csqrt(double x) {
    if (x <= 0.0) return 0.0;
    double g = x > 1.0 ? x : 1.0;
    for (int it = 0; it < 100; ++it) g = 0.5 * (g + x / g);
    return g;
}

__host__ __device__ constexpr int imax3(int a, int b, int c) { int m = a; if (b > m) m = b; if (c > m) m = c; return m; }
__host__ __device__ constexpr int imin3(int a, int b, int c) { int m = a; if (b < m) m = b; if (c < m) m = c; return m; }
__host__ __device__ constexpr int iabs_(int a) { return a < 0 ? -a : a; }
__host__ __device__ constexpr double dabs_(double a) { return a < 0.0 ? -a : a; }

// Complex Clebsch-Gordan <l1 m1 l2 m2 | l3 m3> via Racah formula
__host__ __device__ constexpr double cg_complex(int l1, int m1, int l2, int m2, int l3, int m3) {
    if (m1 + m2 != m3 || l3 < iabs_(l1 - l2) || l3 > l1 + l2) return 0.0;
    double pre = csqrt((double)(2 * l3 + 1) * cfact(l1 + l2 - l3) * cfact(l1 - l2 + l3) *
                       cfact(-l1 + l2 + l3) / cfact(l1 + l2 + l3 + 1));
    pre *= csqrt(cfact(l1 + m1) * cfact(l1 - m1) * cfact(l2 + m2) * cfact(l2 - m2) *
                 cfact(l3 + m3) * cfact(l3 - m3));
    int kmin = imax3(0, l2 - l3 - m1, l1 - l3 + m2);
    int kmax = imin3(l1 + l2 - l3, l1 - m1, l2 + m2);
    double s = 0.0;
    for (int k = kmin; k <= kmax; ++k) {
        double d = cfact(k) * cfact(l1 + l2 - l3 - k) * cfact(l1 - m1 - k) *
                   cfact(l2 + m2 - k) * cfact(l3 - l2 + m1 + k) * cfact(l3 - l1 - m2 + k);
        s += ((k & 1) ? -1.0 : 1.0) / d;
    }
    return pre * s;
}

template <int L1, int L2, int L3>
struct CGT {
    double v[2 * L1 + 1][2 * L2 + 1][2 * L3 + 1];
};

// Real-basis CG tensor (exact port of reference: .imag if it dominates, else .real)
template <int L1, int L2, int L3>
__host__ __device__ constexpr CGT<L1, L2, L3> make_cg() {
    constexpr int NA = 2 * L1 + 1, NB = 2 * L2 + 1, NC = 2 * L3 + 1;
    const double is2 = 1.0 / csqrt(2.0);

    double Ur[3][7][7] = {};
    double Ui[3][7][7] = {};
    int Ls[3] = {L1, L2, L3};
    for (int t = 0; t < 3; ++t) {
        int l = Ls[t];
        for (int mp = -l; mp <= l; ++mp) {
            int r = mp + l;
            if (mp > 0) {
                Ur[t][r][mp + l]  = ((mp & 1) ? -1.0 : 1.0) * is2;
                Ur[t][r][-mp + l] = is2;
            } else if (mp == 0) {
                Ur[t][r][l] = 1.0;
            } else {
                Ui[t][r][mp + l]  = is2;
                Ui[t][r][-mp + l] = -(((-mp) & 1) ? -1.0 : 1.0) * is2;
            }
        }
    }

    double Cc[7][7][7] = {};
    for (int m = 0; m < NA; ++m)
        for (int n = 0; n < NB; ++n)
            for (int o = 0; o < NC; ++o)
                Cc[m][n][o] = cg_complex(L1, m - L1, L2, n - L2, L3, o - L3);

    double Tre[NA][NB][NC] = {};
    double Tim[NA][NB][NC] = {};
    double maxre = 0.0, maxim = 0.0;
    for (int a = 0; a < NA; ++a)
        for (int b = 0; b < NB; ++b)
            for (int c = 0; c < NC; ++c) {
                double are = 0.0, aim = 0.0;
                for (int m = 0; m < NA; ++m)
                    for (int n = 0; n < NB; ++n) {
                        int o = (m - L1) + (n - L2) + L3;
                        if (o < 0 || o >= NC) continue;
                        double cc = Cc[m][n][o];
                        if (cc == 0.0) continue;
                        double xr = Ur[0][a][m], xi = Ui[0][a][m];
                        double yr = Ur[1][b][n], yi = Ui[1][b][n];
                        double zr = Ur[2][c][o], zi = -Ui[2][c][o];
                        double pr = xr * yr - xi * yi;
                        double pi = xr * yi + xi * yr;
                        double tr = pr * zr - pi * zi;
                        double ti = pr * zi + pi * zr;
                        are += tr * cc;
                        aim += ti * cc;
                    }
                Tre[a][b][c] = are;
                Tim[a][b][c] = aim;
                if (dabs_(are) > maxre) maxre = dabs_(are);
                if (dabs_(aim) > maxim) maxim = dabs_(aim);
            }

    CGT<L1, L2, L3> R = {};
    bool useim = maxim > maxre;
    for (int a = 0; a < NA; ++a)
        for (int b = 0; b < NB; ++b)
            for (int c = 0; c < NC; ++c)
                R.v[a][b][c] = useim ? Tim[a][b][c] : Tre[a][b][c];
    return R;
}

// Exchange sign sigma s.t. T(L2,L1,L3)[b][a][c] == sigma * T(L1,L2,L3)[a][b][c]
template <int L1, int L2, int L3>
__host__ __device__ constexpr double exch_sign() {
    CGT<L1, L2, L3> A = make_cg<L1, L2, L3>();
    CGT<L2, L1, L3> B = make_cg<L2, L1, L3>();
    for (int a = 0; a < 2 * L1 + 1; ++a)
        for (int b = 0; b < 2 * L2 + 1; ++b)
            for (int c = 0; c < 2 * L3 + 1; ++c)
                if (dabs_(A.v[a][b][c]) > 1e-9)
                    return B.v[b][a][c] / A.v[a][b][c];
    return 0.0;
}

// Does the symmetrized (self-coupling) tensor have any nonzero?
template <int L, int L3>
__host__ __device__ constexpr bool sym_any() {
    CGT<L, L, L3> T = make_cg<L, L, L3>();
    for (int a = 0; a < 2 * L + 1; ++a)
        for (int b = a; b < 2 * L + 1; ++b)
            for (int c = 0; c < 2 * L3 + 1; ++c) {
                double w = (a == b) ? T.v[a][b][c] : (T.v[a][b][c] + T.v[b][a][c]);
                if (dabs_(w) > 1e-12) return true;
            }
    return false;
}

// ============================================================================
// Contractions. CG weights are compile-time constants; ~zero terms are DCE'd,
// surviving terms become FFMA with immediate multipliers.
// ============================================================================

template <int L1, int L2, int L3>
__device__ __forceinline__ void acc_path(float scale, const float* u, const float* v, float* o) {
    constexpr CGT<L1, L2, L3> T = make_cg<L1, L2, L3>();
    float tmp[2 * L3 + 1];
#pragma unroll
    for (int c = 0; c < 2 * L3 + 1; ++c) tmp[c] = 0.0f;
#pragma unroll
    for (int a = 0; a < 2 * L1 + 1; ++a) {
#pragma unroll
        for (int b = 0; b < 2 * L2 + 1; ++b) {
            float p = u[a] * v[b];
#pragma unroll
            for (int c = 0; c < 2 * L3 + 1; ++c) {
                constexpr double EPS = 1e-12;
                double wd = T.v[a][b][c];
                if (wd > EPS || wd < -EPS) tmp[c] = fmaf((float)wd, p, tmp[c]);
            }
        }
    }
#pragma unroll
    for (int c = 0; c < 2 * L3 + 1; ++c) o[c] = fmaf(scale, tmp[c], o[c]);
}

// Self-coupling, symmetrized over (a,b): products only for a<=b; fully
// antisymmetric paths drop at compile time.
template <int L, int L3>
__device__ __forceinline__ void acc_sym(float scale, const float* u, float* o) {
    if constexpr (!sym_any<L, L3>()) return;
    constexpr CGT<L, L, L3> T = make_cg<L, L, L3>();
    float tmp[2 * L3 + 1];
#pragma unroll
    for (int c = 0; c < 2 * L3 + 1; ++c) tmp[c] = 0.0f;
#pragma unroll
    for (int a = 0; a < 2 * L + 1; ++a) {
#pragma unroll
        for (int b = a; b < 2 * L + 1; ++b) {
            float p = u[a] * u[b];
#pragma unroll
            for (int c = 0; c < 2 * L3 + 1; ++c) {
                constexpr double EPS = 1e-12;
                double wd = (a == b) ? T.v[a][b][c] : (T.v[a][b][c] + T.v[b][a][c]);
                if (wd > EPS || wd < -EPS) tmp[c] = fmaf((float)wd, p, tmp[c]);
            }
        }
    }
#pragma unroll
    for (int c = 0; c < 2 * L3 + 1; ++c) o[c] = fmaf(scale, tmp[c], o[c]);
}

// ============================================================================
// cp.async helpers (register-free global->shared staging)
// ============================================================================
__device__ __forceinline__ void cp_async16(unsigned dst_smem, const void* src) {
    asm volatile("cp.async.cg.shared.global [%0], [%1], 16;" :: "r"(dst_smem), "l"(src));
}
__device__ __forceinline__ void cp_async_commit() {
    asm volatile("cp.async.commit_group;");
}
template <int N>
__device__ __forceinline__ void cp_async_wait() {
    asm volatile("cp.async.wait_group %0;" :: "n"(N));
}

// ============================================================================
// Kernel. Layout facts (METADATA=[64,48,32], MAX_L=3):
//   OFF_IN = {0,64,208}, DIM_IN=368; OFF_OUT={0,64,208,448}, DIM_OUT=672
//   mix base offsets (PATHS order):
//     (0,0,0):0 (0,1,1):64 (0,2,2):112 (1,0,1):144 (1,1,0):192 (1,1,1):240
//     (1,1,2):288 (1,2,1):336 (1,2,2):368 (1,2,3):400 (2,0,2):432 (2,1,1):464
//     (2,1,2):496 (2,1,3):528 (2,2,0):560 (2,2,1):592 (2,2,2):624 (2,2,3):656
//   keep bases: l0->0, l1->64, l2->112
//
// WARP-AUTONOMOUS, 4 ROWS PER WARP, cp.async DOUBLE-BUFFERED INPUT:
// coefficients (incl. fused mirror-pair scales) loaded ONCE per warp into
// registers; rows stream through two warp-private x slots via cp.async
// (no prefetch registers), overlapping row r+1's load with row r's compute.
// Thread i handles HEAVY channel i (full path set) and LIGHT channel 32+i
// (l0 always; l1 iff i<16). Unique writer per output element; no atomics;
// intra-warp sync only.
// ============================================================================

#define TPB 256
#define WARPS_PB (TPB / 32)     // 8 warps per block
#define ROWS_PW 4               // rows per warp
#define DIN 368                 // 92 float4
#define DOUT 672                // 168 float4
#define XSLOT4 (DIN / 4)        // 92
#define OSLOT4 (DOUT / 4)       // 168
#define WSLOT4 (2 * XSLOT4 + OSLOT4)   // 352 float4 = 5632 B per warp

__global__ void __launch_bounds__(TPB) selfmix_kernel(
    const float* __restrict__ x, const float* __restrict__ keepc,
    const float* __restrict__ mixc, float* __restrict__ out, int n)
{
    __shared__ float4 smem4[WARPS_PB * WSLOT4];   // 45056 B

    int w = threadIdx.x >> 5;
    int lane = threadIdx.x & 31;
    int base = (blockIdx.x * WARPS_PB + w) * ROWS_PW;
    if (base >= n) return;

    float4* xsA = smem4 + w * WSLOT4;     // x slot 0
    float4* xsB = xsA + XSLOT4;           // x slot 1
    float4* ow4 = xsB + XSLOT4;           // output slot
    float* orow = (float*)ow4;

    int i = lane;        // heavy channel
    int j = 32 + i;      // light channel

    constexpr float S011 = (float)exch_sign<0, 1, 1>();
    constexpr float S022 = (float)exch_sign<0, 2, 2>();
    constexpr float S121 = (float)exch_sign<1, 2, 1>();
    constexpr float S122 = (float)exch_sign<1, 2, 2>();
    constexpr float S123 = (float)exch_sign<1, 2, 3>();

    // register-free prefetch of one row into a warp-private x slot
    auto prefetch = [&](float4* slot, int row) {
        const float4* src = (const float4*)(x + (long long)row * DIN);
        unsigned ds = (unsigned)__cvta_generic_to_shared(slot);
        cp_async16(ds + lane * 16, src + lane);
        cp_async16(ds + (lane + 32) * 16, src + lane + 32);
        if (lane < XSLOT4 - 64) cp_async16(ds + (lane + 64) * 16, src + lane + 64);
        cp_async_commit();
    };

    // ---- row-invariant coefficients, loaded once per warp ----
    // light channel j
    float kc0j = keepc[j];
    float fm000j = 0.5f * mixc[j];
    float kc1j = 0.f, fm011j = 0.f, fm110j = 0.f, fm112j = 0.f;
    if (i < 16) {
        kc1j   = keepc[64 + j];
        fm011j = 0.5f * (mixc[64 + j] + S011 * mixc[144 + j]);
        fm110j = 0.5f * mixc[192 + j];
        fm112j = 0.5f * mixc[288 + j];
    }
    // heavy channel i
    float kc0i = keepc[i];
    float kc1i = keepc[64 + i];
    float kc2i = keepc[112 + i];
    float fm000i = 0.5f * mixc[i];
    float fm011i = 0.5f * (mixc[64 + i] + S011 * mixc[144 + i]);
    float fm110i = 0.5f * mixc[192 + i];
    float fm112i = 0.5f * mixc[288 + i];
    float fm022i = 0.5f * (mixc[112 + i] + S022 * mixc[432 + i]);
    float fm121i = 0.5f * (mixc[336 + i] + S121 * mixc[464 + i]);
    float fm122i = 0.5f * (mixc[368 + i] + S122 * mixc[496 + i]);
    float fm123i = 0.5f * (mixc[400 + i] + S123 * mixc[528 + i]);
    float fm220i = 0.5f * mixc[560 + i];
    float fm222i = 0.5f * mixc[624 + i];

    prefetch(xsA, base);

#pragma unroll
    for (int r = 0; r < ROWS_PW; ++r) {
        int row = base + r;
        if (row >= n) break;

        const float* xr = (const float*)((r & 1) ? xsB : xsA);

        // issue next-row prefetch into the other slot, then wait for this row
        bool has_next = (r + 1 < ROWS_PW) && (row + 1 < n);
        if (has_next) {
            prefetch((r & 1) ? xsA : xsB, row + 1);
            cp_async_wait<1>();   // this row's group done; next still in flight
        } else {
            cp_async_wait<0>();
        }
        __syncwarp();

        // ---------------- LIGHT phase: channel j = 32+i ----------------
        {
            float s2[1] = { xr[j] };
            float o0b[1];
            o0b[0] = s2[0] * kc0j;
            acc_path<0, 0, 0>(fm000j, s2, s2, o0b);

            if (i < 16) {  // l1 channels 32..47
                float u2[3];
#pragma unroll
                for (int m = 0; m < 3; ++m) u2[m] = xr[64 + 3 * j + m];
                float o1b[3];
#pragma unroll
                for (int m = 0; m < 3; ++m) o1b[m] = u2[m] * kc1j;

                acc_path<0, 1, 1>(fm011j, s2, u2, o1b);
                acc_sym<1, 0>(fm110j, u2, o0b);

                float o2b[5];
#pragma unroll
                for (int m = 0; m < 5; ++m) o2b[m] = 0.0f;
                acc_sym<1, 2>(fm112j, u2, o2b);

#pragma unroll
                for (int m = 0; m < 3; ++m) orow[64 + 3 * j + m] = o1b[m];
#pragma unroll
                for (int m = 0; m < 5; ++m) orow[208 + 5 * j + m] = o2b[m];
            }
            orow[j] = o0b[0];
        }

        // ---------------- HEAVY phase: channel i ----------------
        {
            float s[1] = { xr[i] };
            float u[3];
#pragma unroll
            for (int m = 0; m < 3; ++m) u[m] = xr[64 + 3 * i + m];
            float w5[5];
#pragma unroll
            for (int m = 0; m < 5; ++m) w5[m] = xr[208 + 5 * i + m];

            float o0[1];
            o0[0] = s[0] * kc0i;
            acc_path<0, 0, 0>(fm000i, s, s, o0);

            float o1[3];
#pragma unroll
            for (int m = 0; m < 3; ++m) o1[m] = u[m] * kc1i;

            float o2[5];
#pragma unroll
            for (int m = 0; m < 5; ++m) o2[m] = w5[m] * kc2i;

            float o3[7];
#pragma unroll
            for (int m = 0; m < 7; ++m) o3[m] = 0.0f;

            acc_path<0, 1, 1>(fm011i, s, u, o1);
            acc_sym<1, 0>(fm110i, u, o0);
            acc_sym<1, 2>(fm112i, u, o2);

            acc_path<0, 2, 2>(fm022i, s, w5, o2);
            acc_path<1, 2, 1>(fm121i, u, w5, o1);
            acc_path<1, 2, 2>(fm122i, u, w5, o2);
            acc_path<1, 2, 3>(fm123i, u, w5, o3);

            acc_sym<2, 0>(fm220i, w5, o0);
            acc_sym<2, 2>(fm222i, w5, o2);

            orow[i] = o0[0];
#pragma unroll
            for (int m = 0; m < 3; ++m) orow[64 + 3 * i + m] = o1[m];
#pragma unroll
            for (int m = 0; m < 5; ++m) orow[208 + 5 * i + m] = o2[m];
#pragma unroll
            for (int m = 0; m < 7; ++m) orow[448 + 7 * i + m] = o3[m];
        }
        __syncwarp();

        // ---- warp-private staged output store ----
        {
            float4* og4 = (float4*)(out + (long long)row * DOUT);
#pragma unroll
            for (int t = lane; t < OSLOT4; t += 32) og4[t] = ow4[t];
        }
        __syncwarp();   // protect output slot (and x slot reuse) for next iter
    }
}

// ============================================================================
// Launch
// ============================================================================
extern "C" void kernel_launch(void* const* d_in, const int* in_sizes, int n_in,
                              void* d_out, int out_size) {
    const float* x     = (const float*)d_in[0];   // [N, 368]
    const float* keepc = (const float*)d_in[1];   // [144]
    const float* mixc  = (const float*)d_in[2];   // [688]
    float* out = (float*)d_out;                   // [N, 672]

    int n = in_sizes[0] / DIN;
    int rows_per_block = WARPS_PB * ROWS_PW;
    int grid = (n + rows_per_block - 1) / rows_per_block;
    selfmix_kernel<<<grid, TPB>>>(x, keepc, mixc, out, n);
}